// round 1
// baseline (speedup 1.0000x reference)
#include <cuda_runtime.h>
#include <cuda_bf16.h>
#include <cstdint>

// ---------------------------------------------------------------------------
// Problem constants (B=1)
// ---------------------------------------------------------------------------
#define N_TOK   768
#define DT      447
#define CS      384
#define CZ      128
#define TFD     831           // DT + CS
#define RELD    139           // 66 + 66 + 1 + 6
#define COUT    640           // 384 (s_init) + 128 (a) + 128 (b)

// d_out layout (flattened tuple, fp32):
//   s_input : [768, 831]            @ 0
//   s_init  : [768, 384]            @ 638208
//   z_init  : [768, 768, 128]       @ 933120
//   rel_feat: [768, 768, 139]       @ 76430592
#define OFF_SINPUT  ((size_t)0)
#define OFF_SINIT   ((size_t)638208)
#define OFF_Z       ((size_t)933120)
#define OFF_REL     ((size_t)76430592)

// Scratch (device globals: allocation-free)
__device__ __align__(16) float g_ab[2 * N_TOK * CZ];     // a then b
__device__ __align__(16) float g_Wt[RELD * CZ];          // W_pos transposed [r][c]

// ---------------------------------------------------------------------------
// Kernel 1: build s_input (concat) + transpose W_pos -> g_Wt
// ---------------------------------------------------------------------------
__global__ void prep_kernel(const float* __restrict__ tf,
                            const float* __restrict__ ta,
                            const float* __restrict__ Wpos,
                            float* __restrict__ out)
{
    int tid = blockIdx.x * blockDim.x + threadIdx.x;
    int nt  = gridDim.x * blockDim.x;

    // s_input copy
    for (int idx = tid; idx < N_TOK * TFD; idx += nt) {
        int n = idx / TFD;
        int d = idx - n * TFD;
        float v = (d < DT) ? tf[n * DT + d] : ta[n * CS + (d - DT)];
        out[OFF_SINPUT + idx] = v;
    }
    // W_pos transpose: Wpos is [CZ][RELD] row-major -> g_Wt [RELD][CZ]
    for (int idx = tid; idx < RELD * CZ; idx += nt) {
        int r = idx >> 7;          // / 128
        int c = idx & 127;
        g_Wt[idx] = Wpos[c * RELD + r];
    }
}

// ---------------------------------------------------------------------------
// Kernel 2: C[768,640] = s_input[768,831] @ Wcat[640,831]^T
//   Wcat rows: [0,384)=W_single, [384,512)=W_left, [512,640)=W_right
//   C columns route to: s_init (d_out), g_ab (a), g_ab+768*128 (b)
// Tiled 64x64, K-tile 16, 256 threads, 4x4 per thread.
// ---------------------------------------------------------------------------
__global__ void gemm_kernel(const float* __restrict__ A,      // s_input
                            const float* __restrict__ Wsingle,
                            const float* __restrict__ Wleft,
                            const float* __restrict__ Wright,
                            float* __restrict__ out)
{
    __shared__ float As[16][68];
    __shared__ float Bs[16][68];

    const int n0 = blockIdx.y * 64;
    const int c0 = blockIdx.x * 64;
    const int tid = threadIdx.x;
    const int tx = tid & 15;          // 0..15 (col group)
    const int ty = tid >> 4;          // 0..15 (row group)

    float acc[4][4];
#pragma unroll
    for (int r = 0; r < 4; ++r)
#pragma unroll
        for (int c = 0; c < 4; ++c) acc[r][c] = 0.f;

    const int kk = tid & 15;
    const int rl = tid >> 4;

    for (int k0 = 0; k0 < TFD; k0 += 16) {
        // load A tile (64 rows x 16 k) and B tile (64 cols x 16 k)
#pragma unroll
        for (int p = 0; p < 4; ++p) {
            int row = rl + p * 16;
            int kg = k0 + kk;
            float av = 0.f, bv = 0.f;
            if (kg < TFD) {
                av = A[(size_t)(n0 + row) * TFD + kg];
                int gc = c0 + row;
                const float* wrow;
                if (gc < 384)      wrow = Wsingle + (size_t)gc * TFD;
                else if (gc < 512) wrow = Wleft   + (size_t)(gc - 384) * TFD;
                else               wrow = Wright  + (size_t)(gc - 512) * TFD;
                bv = wrow[kg];
            }
            As[kk][row] = av;
            Bs[kk][row] = bv;
        }
        __syncthreads();

#pragma unroll
        for (int k = 0; k < 16; ++k) {
            float4 av = *(const float4*)&As[k][ty * 4];
            float4 bv = *(const float4*)&Bs[k][tx * 4];
            acc[0][0] += av.x * bv.x; acc[0][1] += av.x * bv.y;
            acc[0][2] += av.x * bv.z; acc[0][3] += av.x * bv.w;
            acc[1][0] += av.y * bv.x; acc[1][1] += av.y * bv.y;
            acc[1][2] += av.y * bv.z; acc[1][3] += av.y * bv.w;
            acc[2][0] += av.z * bv.x; acc[2][1] += av.z * bv.y;
            acc[2][2] += av.z * bv.z; acc[2][3] += av.z * bv.w;
            acc[3][0] += av.w * bv.x; acc[3][1] += av.w * bv.y;
            acc[3][2] += av.w * bv.z; acc[3][3] += av.w * bv.w;
        }
        __syncthreads();
    }

    // epilogue: route columns
#pragma unroll
    for (int r = 0; r < 4; ++r) {
        int n = n0 + ty * 4 + r;
#pragma unroll
        for (int c = 0; c < 4; ++c) {
            int gc = c0 + tx * 4 + c;
            float v = acc[r][c];
            if (gc < 384) {
                out[OFF_SINIT + (size_t)n * 384 + gc] = v;
            } else if (gc < 512) {
                g_ab[(size_t)n * CZ + (gc - 384)] = v;
            } else {
                g_ab[(size_t)N_TOK * CZ + (size_t)n * CZ + (gc - 512)] = v;
            }
        }
    }
}

// ---------------------------------------------------------------------------
// Kernel 3: fused z_init + rel_feat. One block per i, one warp per j.
// ---------------------------------------------------------------------------
__global__ __launch_bounds__(256, 6)
void fused_z_kernel(const float* __restrict__ contact,
                    const int* __restrict__ ti_g,
                    const int* __restrict__ ri_g,
                    const int* __restrict__ ai_g,
                    const int* __restrict__ ei_g,
                    const int* __restrict__ si_g,
                    const float* __restrict__ Wbond,
                    float* __restrict__ out)
{
    __shared__ int sh_ti[N_TOK], sh_ri[N_TOK], sh_ai[N_TOK], sh_ei[N_TOK], sh_si[N_TOK];

    const int i    = blockIdx.x;
    const int tid  = threadIdx.x;
    const int lane = tid & 31;
    const int wid  = tid >> 5;

    for (int t = tid; t < N_TOK; t += 256) {
        sh_ti[t] = ti_g[t];
        sh_ri[t] = ri_g[t];
        sh_ai[t] = ai_g[t];
        sh_ei[t] = ei_g[t];
        sh_si[t] = si_g[t];
    }
    __syncthreads();

    const int ti = sh_ti[i], ri = sh_ri[i], ai = sh_ai[i], ei = sh_ei[i], si = sh_si[i];

    const int lane4 = lane * 4;
    const float4 a4    = *(const float4*)(g_ab + (size_t)i * CZ + lane4);
    const float4 bond4 = *(const float4*)(Wbond + lane4);
    const float4 w132  = *(const float4*)(g_Wt + 132 * CZ + lane4);

    const float* __restrict__ bmat = g_ab + (size_t)N_TOK * CZ;
    float* __restrict__ zout   = out + OFF_Z   + (size_t)i * N_TOK * CZ;
    float* __restrict__ relout = out + OFF_REL + (size_t)i * N_TOK * RELD;

    for (int j = wid; j < N_TOK; j += 8) {
        const int tj = sh_ti[j], rj = sh_ri[j], aj = sh_ai[j], ej = sh_ei[j], sj = sh_si[j];

        const bool sc   = (ai == aj);
        const bool sres = (ri == rj);
        const bool sent = (ei == ej);

        int rd = ri - rj + 32; rd = rd < 0 ? 0 : (rd > 64 ? 64 : rd); if (!sc) rd = 65;
        int td = ti - tj + 32; td = td < 0 ? 0 : (td > 64 ? 64 : td); if (!(sc && sres)) td = 65;
        int cd = si - sj + 2;  cd = cd < 0 ? 0 : (cd > 4  ? 4  : cd); if (!sent) cd = 5;
        const float sef = sent ? 1.f : 0.f;

        const float4 w1 = __ldg((const float4*)(g_Wt + (size_t)rd * CZ + lane4));
        const float4 w2 = __ldg((const float4*)(g_Wt + (size_t)(66 + td) * CZ + lane4));
        const float4 w4 = __ldg((const float4*)(g_Wt + (size_t)(133 + cd) * CZ + lane4));
        const float4 b4 = __ldg((const float4*)(bmat + (size_t)j * CZ + lane4));
        const float  cm = __ldg(contact + (size_t)i * N_TOK + j);

        float4 z;
        z.x = a4.x + b4.x + w1.x + w2.x + sef * w132.x + w4.x + cm * bond4.x;
        z.y = a4.y + b4.y + w1.y + w2.y + sef * w132.y + w4.y + cm * bond4.y;
        z.z = a4.z + b4.z + w1.z + w2.z + sef * w132.z + w4.z + cm * bond4.z;
        z.w = a4.w + b4.w + w1.w + w2.w + sef * w132.w + w4.w + cm * bond4.w;

        __stcs((float4*)(zout + (size_t)j * CZ + lane4), z);

        // rel_feat row: 139 floats, mostly zero; lanes stripe it.
        float* relrow = relout + (size_t)j * RELD;
        const int t1 = rd, t2 = 66 + td, t4 = 133 + cd;
        int t = lane;
#pragma unroll
        for (int u = 0; u < 5; ++u, t += 32) {
            if (t < RELD) {
                float v = 0.f;
                if (t == t1 || t == t2 || t == t4) v = 1.f;
                else if (t == 132)                v = sef;
                __stcs(relrow + t, v);
            }
        }
    }
}

// ---------------------------------------------------------------------------
// Launch
// ---------------------------------------------------------------------------
extern "C" void kernel_launch(void* const* d_in, const int* in_sizes, int n_in,
                              void* d_out, int out_size)
{
    const float* tf      = (const float*)d_in[0];   // target_feat
    const float* ta      = (const float*)d_in[1];   // token_act
    const float* contact = (const float*)d_in[2];   // contact_matrix
    const int*   ti      = (const int*)  d_in[3];   // token_index
    const int*   ri      = (const int*)  d_in[4];   // residue_index
    const int*   ai      = (const int*)  d_in[5];   // asym_id
    const int*   ei      = (const int*)  d_in[6];   // entity_id
    const int*   si      = (const int*)  d_in[7];   // sym_id
    const float* Wsingle = (const float*)d_in[8];
    const float* Wleft   = (const float*)d_in[9];
    const float* Wright  = (const float*)d_in[10];
    const float* Wpos    = (const float*)d_in[11];
    const float* Wbond   = (const float*)d_in[12];
    float* out = (float*)d_out;

    prep_kernel<<<148, 256>>>(tf, ta, Wpos, out);

    dim3 ggrid(COUT / 64, N_TOK / 64);   // 10 x 12
    gemm_kernel<<<ggrid, 256>>>(out + OFF_SINPUT, Wsingle, Wleft, Wright, out);

    fused_z_kernel<<<N_TOK, 256>>>(contact, ti, ri, ai, ei, si, Wbond, out);
}